// round 3
// baseline (speedup 1.0000x reference)
#include <cuda_runtime.h>
#include <math.h>
#include <stdint.h>

#define NN   100000
#define NE   1600000
#define HID  64
#define K1   136          // 2*HID + EDGE_IN
#define TILE_E 128
#define MLP_GRID 148

// ---------------- f32x2 packed helpers (sm_103a) ----------------
typedef unsigned long long u64;

__device__ __forceinline__ u64 fma2(u64 a, u64 b, u64 c) {
    u64 d;
    asm("fma.rn.f32x2 %0, %1, %2, %3;" : "=l"(d) : "l"(a), "l"(b), "l"(c));
    return d;
}
__device__ __forceinline__ u64 pack2(float lo, float hi) {
    u64 d;
    asm("mov.b64 %0, {%1, %2};" : "=l"(d) : "f"(lo), "f"(hi));
    return d;
}
__device__ __forceinline__ u64 dup2(float f) {
    u64 d;
    asm("mov.b64 %0, {%1, %1};" : "=l"(d) : "f"(f));
    return d;
}
__device__ __forceinline__ float2 unpack2(u64 v) {
    float2 r;
    asm("mov.b64 {%0, %1}, %2;" : "=f"(r.x), "=f"(r.y) : "l"(v));
    return r;
}

// ---------------- scratch ----------------
__device__ float g_deg[NN];
__device__ float g_sum[NN * HID];
__device__ float g_hA[NN * HID];
__device__ float g_hB[NN * HID];

// ---------------- degree count ----------------
__global__ void k_deg(const int* __restrict__ dst) {
    int e = blockIdx.x * blockDim.x + threadIdx.x;
    if (e < NE) atomicAdd(&g_deg[dst[e]], 1.0f);
}

// ---------------- scatter-add of h[src] rows into g_sum[dst] ----------------
template <int F>
__global__ void k_scatter(const float* __restrict__ h,
                          const int* __restrict__ src,
                          const int* __restrict__ dst) {
    const int C = F / 4;
    int idx = blockIdx.x * blockDim.x + threadIdx.x;
    if (idx >= NE * C) return;
    int e = idx / C;
    int c = idx - e * C;
    int s = __ldg(&src[e]);
    int d = __ldg(&dst[e]);
    float4 v = *reinterpret_cast<const float4*>(h + (size_t)s * F + (size_t)c * 4);
    float* p = g_sum + (size_t)d * F + (size_t)c * 4;
    asm volatile("red.global.add.v4.f32 [%0], {%1,%2,%3,%4};"
                 :: "l"(p), "f"(v.x), "f"(v.y), "f"(v.z), "f"(v.w) : "memory");
}

// ---------------- node transform: out = [relu]( (sum*inv)@Wl + bl + hin@Wr ) ----------------
template <int IN, bool RELU>
__global__ __launch_bounds__(128)
void k_node(const float* __restrict__ hin,
            const float* __restrict__ Wl, const float* __restrict__ bl,
            const float* __restrict__ Wr,
            float* __restrict__ hout) {
    __shared__ float sWl[IN * HID];
    __shared__ float sWr[IN * HID];
    __shared__ float sB[HID];
    for (int i = threadIdx.x; i < IN * HID; i += blockDim.x) {
        sWl[i] = Wl[i];
        sWr[i] = Wr[i];
    }
    if (threadIdx.x < HID) sB[threadIdx.x] = bl[threadIdx.x];
    __syncthreads();

    int n = blockIdx.x * blockDim.x + threadIdx.x;
    if (n >= NN) return;

    float inv = 1.0f / fmaxf(g_deg[n], 1.0f);

    u64 acc[HID / 2];                  // packed over output-pairs
#pragma unroll
    for (int j2 = 0; j2 < HID / 2; j2++) acc[j2] = pack2(sB[2 * j2], sB[2 * j2 + 1]);

    const float4* sumv = reinterpret_cast<const float4*>(g_sum + (size_t)n * IN);
    const float4* xv   = reinterpret_cast<const float4*>(hin   + (size_t)n * IN);

#pragma unroll 1
    for (int kc = 0; kc < IN / 4; kc++) {
        float4 mv = sumv[kc];
        float4 rv = xv[kc];
        u64 m[4] = {dup2(mv.x * inv), dup2(mv.y * inv), dup2(mv.z * inv), dup2(mv.w * inv)};
        u64 r[4] = {dup2(rv.x), dup2(rv.y), dup2(rv.z), dup2(rv.w)};
#pragma unroll
        for (int i = 0; i < 4; i++) {
            int k = kc * 4 + i;
            const ulonglong2* wl = reinterpret_cast<const ulonglong2*>(sWl + k * HID);
            const ulonglong2* wr = reinterpret_cast<const ulonglong2*>(sWr + k * HID);
#pragma unroll
            for (int q = 0; q < HID / 4; q++) {   // 16 ulonglong2 = 32 f32x2 pairs
                ulonglong2 a = wl[q];
                ulonglong2 b = wr[q];
                acc[2 * q]     = fma2(m[i], a.x, acc[2 * q]);
                acc[2 * q]     = fma2(r[i], b.x, acc[2 * q]);
                acc[2 * q + 1] = fma2(m[i], a.y, acc[2 * q + 1]);
                acc[2 * q + 1] = fma2(r[i], b.y, acc[2 * q + 1]);
            }
        }
    }

    float4* outp = reinterpret_cast<float4*>(hout + (size_t)n * HID);
#pragma unroll
    for (int j4 = 0; j4 < HID / 4; j4++) {
        float2 lo = unpack2(acc[2 * j4]);
        float2 hi = unpack2(acc[2 * j4 + 1]);
        float4 o;
        o.x = lo.x; o.y = lo.y; o.z = hi.x; o.w = hi.y;
        if (RELU) {
            o.x = fmaxf(o.x, 0.0f); o.y = fmaxf(o.y, 0.0f);
            o.z = fmaxf(o.z, 0.0f); o.w = fmaxf(o.w, 0.0f);
        }
        outp[j4] = o;
    }
}

// ---------------- edge MLP ----------------
// smem (floats):
//   sInT [K1][128]      transposed inputs
//   sW1d [K1][128]      W1 with each weight duplicated: (w_j, w_j) pairs
//   sZ1T [64][128]
//   sW2d [64][64]       W2 duplicated pairs
//   sZ2T [32][128]
//   sW3[32], sB1[64], sB2[32], sSrc[128], sDst[128]
#define EDGE_SMEM_FLOATS (K1*TILE_E + K1*TILE_E + 64*TILE_E + 64*64 + 32*TILE_E + 32 + 64 + 32)
#define EDGE_SMEM_BYTES  (EDGE_SMEM_FLOATS*4 + 2*TILE_E*4)

__global__ __launch_bounds__(256)
void k_edge_mlp(const float* __restrict__ h,
                const int* __restrict__ src, const int* __restrict__ dst,
                const float* __restrict__ ea,
                const float* __restrict__ W1, const float* __restrict__ b1,
                const float* __restrict__ W2, const float* __restrict__ b2,
                const float* __restrict__ W3, const float* __restrict__ b3,
                float* __restrict__ out) {
    extern __shared__ float sm[];
    float* sInT = sm;                          // K1*128
    float* sW1d = sInT + K1 * TILE_E;          // K1*128
    float* sZ1T = sW1d + K1 * TILE_E;          // 64*128
    float* sW2d = sZ1T + 64 * TILE_E;          // 64*64
    float* sZ2T = sW2d + 64 * 64;              // 32*128
    float* sW3  = sZ2T + 32 * TILE_E;          // 32
    float* sB1  = sW3 + 32;                    // 64
    float* sB2  = sB1 + 64;                    // 32
    int*   sSrc = reinterpret_cast<int*>(sB2 + 32);
    int*   sDst = sSrc + TILE_E;

    const int tid = threadIdx.x;

    // stage weights once per block (persistent blocks, grid=148)
    for (int i = tid; i < K1 * 64; i += 256) {
        int k = i >> 6, j = i & 63;
        float v = W1[i];
        sW1d[(k << 7) + 2 * j]     = v;
        sW1d[(k << 7) + 2 * j + 1] = v;
    }
    for (int i = tid; i < 64 * 32; i += 256) {
        int k = i >> 5, j = i & 31;
        float v = W2[i];
        sW2d[(k << 6) + 2 * j]     = v;
        sW2d[(k << 6) + 2 * j + 1] = v;
    }
    if (tid < 32) sW3[tid] = W3[tid];
    if (tid < 64) sB1[tid] = b1[tid];
    if (tid < 32) sB2[tid] = b2[tid];
    const float bias3 = __ldg(&b3[0]);

    // stage-1 mapping: 16 edge-groups x 16 out-groups; 8 edges x 4 outs / thread
    const int eg1 = tid & 15, jg1 = tid >> 4;
    // stage-2 mapping: 32 edge-groups x 8 out-groups; 4 edges x 4 outs / thread
    const int eg2 = tid & 31, jg2 = tid >> 5;

    const int n_tiles = NE / TILE_E;   // 12500 exact
    for (int tile = blockIdx.x; tile < n_tiles; tile += gridDim.x) {
        const int e0 = tile * TILE_E;
        __syncthreads();
        if (tid < TILE_E) {
            sSrc[tid] = src[e0 + tid];
            sDst[tid] = dst[e0 + tid];
        }
        __syncthreads();

        // gather -> sInT[k][e]
        for (int idx = tid; idx < 34 * TILE_E; idx += 256) {
            int c = idx >> 7;
            int e = idx & 127;
            float4 v;
            if (c < 16)       v = *reinterpret_cast<const float4*>(h + (size_t)sSrc[e] * HID + (size_t)c * 4);
            else if (c < 32)  v = *reinterpret_cast<const float4*>(h + (size_t)sDst[e] * HID + (size_t)(c - 16) * 4);
            else              v = *reinterpret_cast<const float4*>(ea + (size_t)(e0 + e) * 8 + (size_t)(c - 32) * 4);
            int k = c * 4;
            sInT[(k + 0) * TILE_E + e] = v.x;
            sInT[(k + 1) * TILE_E + e] = v.y;
            sInT[(k + 2) * TILE_E + e] = v.z;
            sInT[(k + 3) * TILE_E + e] = v.w;
        }
        __syncthreads();

        // stage 1: z1 = relu(In @ W1 + b1)  -- f32x2 packed over edge pairs
        {
            u64 acc[4][4];
#pragma unroll
            for (int jj = 0; jj < 4; jj++) {
                u64 b = dup2(sB1[4 * jg1 + jj]);
#pragma unroll
                for (int i = 0; i < 4; i++) acc[i][jj] = b;
            }
            const float* aRow = sInT + 8 * eg1;
            const float* wRow = sW1d + 8 * jg1;
#pragma unroll 2
            for (int k = 0; k < K1; k++) {
                ulonglong2 aA = *reinterpret_cast<const ulonglong2*>(aRow + (k << 7));      // edges +0..3
                ulonglong2 aB = *reinterpret_cast<const ulonglong2*>(aRow + (k << 7) + 4);  // edges +4..7
                ulonglong2 wA = *reinterpret_cast<const ulonglong2*>(wRow + (k << 7));      // outs 0,1 (dup)
                ulonglong2 wB = *reinterpret_cast<const ulonglong2*>(wRow + (k << 7) + 4);  // outs 2,3 (dup)
                acc[0][0] = fma2(aA.x, wA.x, acc[0][0]);
                acc[0][1] = fma2(aA.x, wA.y, acc[0][1]);
                acc[0][2] = fma2(aA.x, wB.x, acc[0][2]);
                acc[0][3] = fma2(aA.x, wB.y, acc[0][3]);
                acc[1][0] = fma2(aA.y, wA.x, acc[1][0]);
                acc[1][1] = fma2(aA.y, wA.y, acc[1][1]);
                acc[1][2] = fma2(aA.y, wB.x, acc[1][2]);
                acc[1][3] = fma2(aA.y, wB.y, acc[1][3]);
                acc[2][0] = fma2(aB.x, wA.x, acc[2][0]);
                acc[2][1] = fma2(aB.x, wA.y, acc[2][1]);
                acc[2][2] = fma2(aB.x, wB.x, acc[2][2]);
                acc[2][3] = fma2(aB.x, wB.y, acc[2][3]);
                acc[3][0] = fma2(aB.y, wA.x, acc[3][0]);
                acc[3][1] = fma2(aB.y, wA.y, acc[3][1]);
                acc[3][2] = fma2(aB.y, wB.x, acc[3][2]);
                acc[3][3] = fma2(aB.y, wB.y, acc[3][3]);
            }
#pragma unroll
            for (int jj = 0; jj < 4; jj++)
#pragma unroll
                for (int i = 0; i < 4; i++) {
                    float2 v = unpack2(acc[i][jj]);
                    v.x = fmaxf(v.x, 0.0f);
                    v.y = fmaxf(v.y, 0.0f);
                    *reinterpret_cast<float2*>(sZ1T + (4 * jg1 + jj) * TILE_E + 8 * eg1 + 2 * i) = v;
                }
        }
        __syncthreads();

        // stage 2: z2 = relu(z1 @ W2 + b2)
        {
            u64 acc[2][4];
#pragma unroll
            for (int jj = 0; jj < 4; jj++) {
                u64 b = dup2(sB2[4 * jg2 + jj]);
                acc[0][jj] = b;
                acc[1][jj] = b;
            }
            const float* aRow = sZ1T + 4 * eg2;
            const float* wRow = sW2d + 8 * jg2;
#pragma unroll 4
            for (int k = 0; k < 64; k++) {
                ulonglong2 a  = *reinterpret_cast<const ulonglong2*>(aRow + (k << 7));      // edges +0..3
                ulonglong2 wA = *reinterpret_cast<const ulonglong2*>(wRow + (k << 6));      // outs 0,1 (dup)
                ulonglong2 wB = *reinterpret_cast<const ulonglong2*>(wRow + (k << 6) + 4);  // outs 2,3 (dup)
                acc[0][0] = fma2(a.x, wA.x, acc[0][0]);
                acc[0][1] = fma2(a.x, wA.y, acc[0][1]);
                acc[0][2] = fma2(a.x, wB.x, acc[0][2]);
                acc[0][3] = fma2(a.x, wB.y, acc[0][3]);
                acc[1][0] = fma2(a.y, wA.x, acc[1][0]);
                acc[1][1] = fma2(a.y, wA.y, acc[1][1]);
                acc[1][2] = fma2(a.y, wB.x, acc[1][2]);
                acc[1][3] = fma2(a.y, wB.y, acc[1][3]);
            }
#pragma unroll
            for (int jj = 0; jj < 4; jj++)
#pragma unroll
                for (int i = 0; i < 2; i++) {
                    float2 v = unpack2(acc[i][jj]);
                    v.x = fmaxf(v.x, 0.0f);
                    v.y = fmaxf(v.y, 0.0f);
                    *reinterpret_cast<float2*>(sZ2T + (4 * jg2 + jj) * TILE_E + 4 * eg2 + 2 * i) = v;
                }
        }
        __syncthreads();

        // stage 3: out[e] = sigmoid(z2 . W3 + b3)
        if (tid < TILE_E) {
            float s = bias3;
#pragma unroll
            for (int k = 0; k < 32; k++) s += sZ2T[k * TILE_E + tid] * sW3[k];
            out[e0 + tid] = 1.0f / (1.0f + expf(-s));
        }
    }
}

// ---------------- launch ----------------
extern "C" void kernel_launch(void* const* d_in, const int* in_sizes, int n_in,
                              void* d_out, int out_size) {
    (void)in_sizes; (void)n_in; (void)out_size;
    const float* x   = (const float*)d_in[0];
    const int*   ei  = (const int*)d_in[1];
    const float* ea  = (const float*)d_in[2];
    const float* Wl0 = (const float*)d_in[3];
    const float* bl0 = (const float*)d_in[4];
    const float* Wr0 = (const float*)d_in[5];
    const float* Wl1 = (const float*)d_in[6];
    const float* bl1 = (const float*)d_in[7];
    const float* Wr1 = (const float*)d_in[8];
    const float* Wl2 = (const float*)d_in[9];
    const float* bl2 = (const float*)d_in[10];
    const float* Wr2 = (const float*)d_in[11];
    const float* W1  = (const float*)d_in[12];
    const float* b1  = (const float*)d_in[13];
    const float* W2  = (const float*)d_in[14];
    const float* b2  = (const float*)d_in[15];
    const float* W3  = (const float*)d_in[16];
    const float* b3  = (const float*)d_in[17];
    float* out = (float*)d_out;

    const int* src = ei;
    const int* dst = ei + NE;

    void *p_deg, *p_sum, *p_hA, *p_hB;
    cudaGetSymbolAddress(&p_deg, g_deg);
    cudaGetSymbolAddress(&p_sum, g_sum);
    cudaGetSymbolAddress(&p_hA, g_hA);
    cudaGetSymbolAddress(&p_hB, g_hB);
    float* hA = (float*)p_hA;
    float* hB = (float*)p_hB;

    cudaFuncSetAttribute(k_edge_mlp, cudaFuncAttributeMaxDynamicSharedMemorySize,
                         EDGE_SMEM_BYTES);

    cudaMemsetAsync(p_deg, 0, NN * sizeof(float), 0);
    cudaMemsetAsync(p_sum, 0, (size_t)NN * 32 * sizeof(float), 0);
    k_deg<<<(NE + 255) / 256, 256>>>(dst);

    // layer 0: IN=32
    k_scatter<32><<<(NE * 8 + 255) / 256, 256>>>(x, src, dst);
    k_node<32, true><<<(NN + 127) / 128, 128>>>(x, Wl0, bl0, Wr0, hA);

    // layer 1: IN=64
    cudaMemsetAsync(p_sum, 0, (size_t)NN * 64 * sizeof(float), 0);
    k_scatter<64><<<(NE * 16 + 255) / 256, 256>>>(hA, src, dst);
    k_node<64, true><<<(NN + 127) / 128, 128>>>(hA, Wl1, bl1, Wr1, hB);

    // layer 2: IN=64, no relu
    cudaMemsetAsync(p_sum, 0, (size_t)NN * 64 * sizeof(float), 0);
    k_scatter<64><<<(NE * 16 + 255) / 256, 256>>>(hB, src, dst);
    k_node<64, false><<<(NN + 127) / 128, 128>>>(hB, Wl2, bl2, Wr2, hA);

    // edge predictor
    k_edge_mlp<<<MLP_GRID, 256, EDGE_SMEM_BYTES>>>(hA, src, dst, ea,
                                                   W1, b1, W2, b2, W3, b3, out);
}

// round 4
// speedup vs baseline: 1.9637x; 1.9637x over previous
#include <cuda_runtime.h>
#include <math.h>
#include <stdint.h>

#define NN   100000
#define NE   1600000
#define HID  64
#define K1   136          // 2*HID + EDGE_IN
#define TILE_E 64
#define MLP_GRID 296      // 2 blocks per SM (148 SMs)

// ---------------- scratch (static device allocations, allowed) ----------------
__device__ float g_deg[NN];
__device__ float g_sum[NN * HID];
__device__ float g_hA[NN * HID];
__device__ float g_hB[NN * HID];

// ---------------- degree count ----------------
__global__ void k_deg(const int* __restrict__ dst) {
    int e = blockIdx.x * blockDim.x + threadIdx.x;
    if (e < NE) atomicAdd(&g_deg[dst[e]], 1.0f);
}

// ---------------- scatter-add of h[src] rows into g_sum[dst] ----------------
template <int F>
__global__ void k_scatter(const float* __restrict__ h,
                          const int* __restrict__ src,
                          const int* __restrict__ dst) {
    const int C = F / 4;                       // float4 chunks per row
    int idx = blockIdx.x * blockDim.x + threadIdx.x;
    if (idx >= NE * C) return;
    int e = idx / C;
    int c = idx - e * C;
    int s = __ldg(&src[e]);
    int d = __ldg(&dst[e]);
    float4 v = *reinterpret_cast<const float4*>(h + (size_t)s * F + (size_t)c * 4);
    float* p = g_sum + (size_t)d * F + (size_t)c * 4;
    asm volatile("red.global.add.v4.f32 [%0], {%1,%2,%3,%4};"
                 :: "l"(p), "f"(v.x), "f"(v.y), "f"(v.z), "f"(v.w) : "memory");
}

// ---------------- node transform: out = [relu]( (sum*inv)@Wl + bl + hin@Wr ) ----------------
template <int IN, bool RELU>
__global__ __launch_bounds__(128)
void k_node(const float* __restrict__ hin,
            const float* __restrict__ Wl, const float* __restrict__ bl,
            const float* __restrict__ Wr,
            float* __restrict__ hout) {
    __shared__ float sWl[IN * HID];
    __shared__ float sWr[IN * HID];
    __shared__ float sB[HID];
    for (int i = threadIdx.x; i < IN * HID; i += blockDim.x) {
        sWl[i] = Wl[i];
        sWr[i] = Wr[i];
    }
    if (threadIdx.x < HID) sB[threadIdx.x] = bl[threadIdx.x];
    __syncthreads();

    int n = blockIdx.x * blockDim.x + threadIdx.x;
    if (n >= NN) return;

    float inv = 1.0f / fmaxf(g_deg[n], 1.0f);

    float acc[HID];
#pragma unroll
    for (int j = 0; j < HID; j++) acc[j] = sB[j];

    const float4* sumv = reinterpret_cast<const float4*>(g_sum + (size_t)n * IN);
    const float4* xv   = reinterpret_cast<const float4*>(hin   + (size_t)n * IN);

#pragma unroll 1
    for (int kc = 0; kc < IN / 4; kc++) {
        float4 mv = sumv[kc];
        float4 rv = xv[kc];
        float m[4] = {mv.x * inv, mv.y * inv, mv.z * inv, mv.w * inv};
        float r[4] = {rv.x, rv.y, rv.z, rv.w};
#pragma unroll
        for (int i = 0; i < 4; i++) {
            int k = kc * 4 + i;
            const float4* wl = reinterpret_cast<const float4*>(sWl + k * HID);
            const float4* wr = reinterpret_cast<const float4*>(sWr + k * HID);
#pragma unroll
            for (int j4 = 0; j4 < HID / 4; j4++) {
                float4 a = wl[j4];
                float4 b = wr[j4];
                acc[j4 * 4 + 0] += m[i] * a.x + r[i] * b.x;
                acc[j4 * 4 + 1] += m[i] * a.y + r[i] * b.y;
                acc[j4 * 4 + 2] += m[i] * a.z + r[i] * b.z;
                acc[j4 * 4 + 3] += m[i] * a.w + r[i] * b.w;
            }
        }
    }

    float4* outp = reinterpret_cast<float4*>(hout + (size_t)n * HID);
#pragma unroll
    for (int j4 = 0; j4 < HID / 4; j4++) {
        float4 o;
        o.x = acc[j4 * 4 + 0];
        o.y = acc[j4 * 4 + 1];
        o.z = acc[j4 * 4 + 2];
        o.w = acc[j4 * 4 + 3];
        if (RELU) {
            o.x = fmaxf(o.x, 0.0f); o.y = fmaxf(o.y, 0.0f);
            o.z = fmaxf(o.z, 0.0f); o.w = fmaxf(o.w, 0.0f);
        }
        outp[j4] = o;
    }
}

// ---------------- edge MLP: sigmoid(relu(relu([h_s,h_d,ea]@W1+b1)@W2+b2)@W3+b3) ----------------
// TILE_E = 64 so that smem ~103KB -> 2 blocks/SM (cross-block gather/compute overlap).
// smem layout (floats):
//   sInT [K1][64]   transposed inputs
//   sW1  [K1][64]
//   sZ1T [64][64]
//   sW2  [64][32]
//   sZ2T [32][64]
//   sW3[32], sB1[64], sB2[32], sSrc[64], sDst[64]
#define EDGE_SMEM_FLOATS (K1*TILE_E + K1*64 + 64*TILE_E + 64*32 + 32*TILE_E + 32 + 64 + 32)
#define EDGE_SMEM_BYTES  (EDGE_SMEM_FLOATS*4 + 2*TILE_E*4)

__global__ __launch_bounds__(256, 2)
void k_edge_mlp(const float* __restrict__ h,
                const int* __restrict__ src, const int* __restrict__ dst,
                const float* __restrict__ ea,
                const float* __restrict__ W1, const float* __restrict__ b1,
                const float* __restrict__ W2, const float* __restrict__ b2,
                const float* __restrict__ W3, const float* __restrict__ b3,
                float* __restrict__ out) {
    extern __shared__ float sm[];
    float* sInT = sm;                        // K1*64
    float* sW1  = sInT + K1 * TILE_E;        // K1*64
    float* sZ1T = sW1 + K1 * 64;             // 64*64
    float* sW2  = sZ1T + 64 * TILE_E;        // 64*32
    float* sZ2T = sW2 + 64 * 32;             // 32*64
    float* sW3  = sZ2T + 32 * TILE_E;        // 32
    float* sB1  = sW3 + 32;                  // 64
    float* sB2  = sB1 + 64;                  // 32
    int*   sSrc = reinterpret_cast<int*>(sB2 + 32);   // 64
    int*   sDst = sSrc + TILE_E;                      // 64

    const int tid = threadIdx.x;

    // stage weights once per block (persistent blocks)
    for (int i = tid; i < K1 * 64; i += 256) sW1[i] = W1[i];
    for (int i = tid; i < 64 * 32; i += 256) sW2[i] = W2[i];
    if (tid < 32) sW3[tid] = W3[tid];
    if (tid < 64) sB1[tid] = b1[tid];
    if (tid < 32) sB2[tid] = b2[tid];
    const float bias3 = __ldg(&b3[0]);

    // stage-1 mapping: lanes sweep edges (conflict-free), jg uniform per warp
    // (weight LDS.128 becomes a broadcast). 2 edges x 8 outs per thread.
    const int eg1 = tid & 31;        // edge lane: edges eg1, eg1+32
    const int jg1 = tid >> 5;        // out group: outs jg1*8 .. jg1*8+7
    // stage-2 mapping: 1 edge x 8 outs per thread
    const int eg2 = tid & 63;
    const int jg2 = tid >> 6;

    const int n_tiles = NE / TILE_E;   // 25000 exact
    for (int tile = blockIdx.x; tile < n_tiles; tile += gridDim.x) {
        const int e0 = tile * TILE_E;
        __syncthreads();
        if (tid < TILE_E) {
            sSrc[tid] = src[e0 + tid];
            sDst[tid] = dst[e0 + tid];
        }
        __syncthreads();

        // gather -> sInT[k][e] (34 float4 chunks per edge)
        for (int idx = tid; idx < 34 * TILE_E; idx += 256) {
            int c = idx >> 6;          // chunk 0..33
            int e = idx & 63;
            float4 v;
            if (c < 16)       v = *reinterpret_cast<const float4*>(h + (size_t)sSrc[e] * HID + (size_t)c * 4);
            else if (c < 32)  v = *reinterpret_cast<const float4*>(h + (size_t)sDst[e] * HID + (size_t)(c - 16) * 4);
            else              v = *reinterpret_cast<const float4*>(ea + (size_t)(e0 + e) * 8 + (size_t)(c - 32) * 4);
            int k = c * 4;
            sInT[(k + 0) * TILE_E + e] = v.x;
            sInT[(k + 1) * TILE_E + e] = v.y;
            sInT[(k + 2) * TILE_E + e] = v.z;
            sInT[(k + 3) * TILE_E + e] = v.w;
        }
        __syncthreads();

        // stage 1: z1[64][64] = relu(In @ W1 + b1), 2 edges x 8 outs / thread
        {
            const int j0 = jg1 * 8;
            float acc[2][8];
#pragma unroll
            for (int i = 0; i < 2; i++)
#pragma unroll
                for (int jj = 0; jj < 8; jj++) acc[i][jj] = sB1[j0 + jj];

#pragma unroll 4
            for (int k = 0; k < K1; k++) {
                float a0 = sInT[k * TILE_E + eg1];
                float a1 = sInT[k * TILE_E + eg1 + 32];
                float4 wA = *reinterpret_cast<const float4*>(sW1 + k * 64 + j0);      // broadcast
                float4 wB = *reinterpret_cast<const float4*>(sW1 + k * 64 + j0 + 4);  // broadcast
                float w[8] = {wA.x, wA.y, wA.z, wA.w, wB.x, wB.y, wB.z, wB.w};
#pragma unroll
                for (int jj = 0; jj < 8; jj++) {
                    acc[0][jj] += a0 * w[jj];
                    acc[1][jj] += a1 * w[jj];
                }
            }
#pragma unroll
            for (int jj = 0; jj < 8; jj++)
#pragma unroll
                for (int i = 0; i < 2; i++)
                    sZ1T[(j0 + jj) * TILE_E + eg1 + 32 * i] = fmaxf(acc[i][jj], 0.0f);
        }
        __syncthreads();

        // stage 2: z2[64][32] = relu(z1 @ W2 + b2), 1 edge x 8 outs / thread
        {
            const int j0 = jg2 * 8;
            float acc[8];
#pragma unroll
            for (int jj = 0; jj < 8; jj++) acc[jj] = sB2[j0 + jj];

#pragma unroll 4
            for (int k = 0; k < 64; k++) {
                float a = sZ1T[k * TILE_E + eg2];
                float4 wA = *reinterpret_cast<const float4*>(sW2 + k * 32 + j0);      // broadcast
                float4 wB = *reinterpret_cast<const float4*>(sW2 + k * 32 + j0 + 4);  // broadcast
                acc[0] += a * wA.x;
                acc[1] += a * wA.y;
                acc[2] += a * wA.z;
                acc[3] += a * wA.w;
                acc[4] += a * wB.x;
                acc[5] += a * wB.y;
                acc[6] += a * wB.z;
                acc[7] += a * wB.w;
            }
#pragma unroll
            for (int jj = 0; jj < 8; jj++)
                sZ2T[(j0 + jj) * TILE_E + eg2] = fmaxf(acc[jj], 0.0f);
        }
        __syncthreads();

        // stage 3: out[e] = sigmoid(z2 . W3 + b3)
        if (tid < TILE_E) {
            float s = bias3;
#pragma unroll
            for (int k = 0; k < 32; k++) s += sZ2T[k * TILE_E + tid] * sW3[k];
            out[e0 + tid] = 1.0f / (1.0f + expf(-s));
        }
    }
}

// ---------------- launch ----------------
extern "C" void kernel_launch(void* const* d_in, const int* in_sizes, int n_in,
                              void* d_out, int out_size) {
    (void)in_sizes; (void)n_in; (void)out_size;
    const float* x   = (const float*)d_in[0];
    const int*   ei  = (const int*)d_in[1];
    const float* ea  = (const float*)d_in[2];
    const float* Wl0 = (const float*)d_in[3];
    const float* bl0 = (const float*)d_in[4];
    const float* Wr0 = (const float*)d_in[5];
    const float* Wl1 = (const float*)d_in[6];
    const float* bl1 = (const float*)d_in[7];
    const float* Wr1 = (const float*)d_in[8];
    const float* Wl2 = (const float*)d_in[9];
    const float* bl2 = (const float*)d_in[10];
    const float* Wr2 = (const float*)d_in[11];
    const float* W1  = (const float*)d_in[12];
    const float* b1  = (const float*)d_in[13];
    const float* W2  = (const float*)d_in[14];
    const float* b2  = (const float*)d_in[15];
    const float* W3  = (const float*)d_in[16];
    const float* b3  = (const float*)d_in[17];
    float* out = (float*)d_out;

    const int* src = ei;
    const int* dst = ei + NE;

    void *p_deg, *p_sum, *p_hA, *p_hB;
    cudaGetSymbolAddress(&p_deg, g_deg);
    cudaGetSymbolAddress(&p_sum, g_sum);
    cudaGetSymbolAddress(&p_hA, g_hA);
    cudaGetSymbolAddress(&p_hB, g_hB);
    float* hA = (float*)p_hA;
    float* hB = (float*)p_hB;

    cudaFuncSetAttribute(k_edge_mlp, cudaFuncAttributeMaxDynamicSharedMemorySize,
                         EDGE_SMEM_BYTES);

    // degree (shared by all 3 layers) + layer-0 sum
    cudaMemsetAsync(p_deg, 0, NN * sizeof(float), 0);
    cudaMemsetAsync(p_sum, 0, (size_t)NN * 32 * sizeof(float), 0);
    k_deg<<<(NE + 255) / 256, 256>>>(dst);

    // layer 0: IN=32
    k_scatter<32><<<(NE * 8 + 255) / 256, 256>>>(x, src, dst);
    k_node<32, true><<<(NN + 127) / 128, 128>>>(x, Wl0, bl0, Wr0, hA);

    // layer 1: IN=64
    cudaMemsetAsync(p_sum, 0, (size_t)NN * 64 * sizeof(float), 0);
    k_scatter<64><<<(NE * 16 + 255) / 256, 256>>>(hA, src, dst);
    k_node<64, true><<<(NN + 127) / 128, 128>>>(hA, Wl1, bl1, Wr1, hB);

    // layer 2: IN=64, no relu
    cudaMemsetAsync(p_sum, 0, (size_t)NN * 64 * sizeof(float), 0);
    k_scatter<64><<<(NE * 16 + 255) / 256, 256>>>(hB, src, dst);
    k_node<64, false><<<(NN + 127) / 128, 128>>>(hB, Wl2, bl2, Wr2, hA);

    // edge predictor
    k_edge_mlp<<<MLP_GRID, 256, EDGE_SMEM_BYTES>>>(hA, src, dst, ea,
                                                   W1, b1, W2, b2, W3, b3, out);
}

// round 10
// speedup vs baseline: 3.0148x; 1.5353x over previous
#include <cuda_runtime.h>
#include <cuda_bf16.h>
#include <math.h>
#include <stdint.h>

#define NN   100000
#define NE   1600000
#define HID  64
#define TILE_E 64
#define MLP_GRID 296
#define N_TILES (NE / TILE_E)   // 25000 exact

// strides (bf16 elements) chosen for conflict-free ldmatrix row addressing
#define STRIDE1 152     // A1/B1 rows: 304B; r*304 mod 128 -> distinct 16B groups
#define STRIDE2 72      // Z1/B2 rows: 144B; r*144 mod 128 -> distinct 16B groups
#define Z2_STRIDE 34    // f32 words

// ---------------- mma.sync helpers (baseline PTX, no arch-feature insts) ----------------
__device__ __forceinline__ uint32_t smem_u32(const void* p) {
    uint32_t a;
    asm("{ .reg .u64 t; cvta.to.shared.u64 t, %1; cvt.u32.u64 %0, t; }" : "=r"(a) : "l"(p));
    return a;
}
__device__ __forceinline__ void ldsm4(uint32_t addr, uint32_t r[4]) {
    asm volatile("ldmatrix.sync.aligned.m8n8.x4.shared.b16 {%0,%1,%2,%3}, [%4];"
                 : "=r"(r[0]), "=r"(r[1]), "=r"(r[2]), "=r"(r[3]) : "r"(addr));
}
__device__ __forceinline__ void mma16816(float c[4], const uint32_t a[4],
                                         uint32_t b0, uint32_t b1) {
    asm volatile("mma.sync.aligned.m16n8k16.row.col.f32.bf16.bf16.f32 "
                 "{%0,%1,%2,%3}, {%4,%5,%6,%7}, {%8,%9}, {%0,%1,%2,%3};"
                 : "+f"(c[0]), "+f"(c[1]), "+f"(c[2]), "+f"(c[3])
                 : "r"(a[0]), "r"(a[1]), "r"(a[2]), "r"(a[3]), "r"(b0), "r"(b1));
}
__device__ __forceinline__ void bsplit(float x, __nv_bfloat16& h, __nv_bfloat16& l) {
    h = __float2bfloat16(x);
    l = __float2bfloat16(x - __bfloat162float(h));
}
__device__ __forceinline__ uint32_t packbf2(__nv_bfloat16 a, __nv_bfloat16 b) {
    __nv_bfloat162 t(a, b);
    return *reinterpret_cast<uint32_t*>(&t);
}

// ---------------- scratch ----------------
__device__ float g_deg[NN];
__device__ float g_sum[NN * HID];
__device__ float g_hA[NN * HID];
__device__ float g_hB[NN * HID];

// ---------------- graph kernels (proven R3/R4 versions) ----------------
__global__ void k_deg(const int* __restrict__ dst) {
    int e = blockIdx.x * blockDim.x + threadIdx.x;
    if (e < NE) atomicAdd(&g_deg[dst[e]], 1.0f);
}

template <int F>
__global__ void k_scatter(const float* __restrict__ h,
                          const int* __restrict__ src,
                          const int* __restrict__ dst) {
    const int C = F / 4;
    int idx = blockIdx.x * blockDim.x + threadIdx.x;
    if (idx >= NE * C) return;
    int e = idx / C;
    int c = idx - e * C;
    int s = __ldg(&src[e]);
    int d = __ldg(&dst[e]);
    float4 v = *reinterpret_cast<const float4*>(h + (size_t)s * F + (size_t)c * 4);
    float* p = g_sum + (size_t)d * F + (size_t)c * 4;
    asm volatile("red.global.add.v4.f32 [%0], {%1,%2,%3,%4};"
                 :: "l"(p), "f"(v.x), "f"(v.y), "f"(v.z), "f"(v.w) : "memory");
}

template <int IN, bool RELU>
__global__ __launch_bounds__(128)
void k_node(const float* __restrict__ hin,
            const float* __restrict__ Wl, const float* __restrict__ bl,
            const float* __restrict__ Wr,
            float* __restrict__ hout) {
    __shared__ float sWl[IN * HID];
    __shared__ float sWr[IN * HID];
    __shared__ float sB[HID];
    for (int i = threadIdx.x; i < IN * HID; i += blockDim.x) {
        sWl[i] = Wl[i];
        sWr[i] = Wr[i];
    }
    if (threadIdx.x < HID) sB[threadIdx.x] = bl[threadIdx.x];
    __syncthreads();

    int n = blockIdx.x * blockDim.x + threadIdx.x;
    if (n >= NN) return;

    float inv = 1.0f / fmaxf(g_deg[n], 1.0f);
    float acc[HID];
#pragma unroll
    for (int j = 0; j < HID; j++) acc[j] = sB[j];

    const float4* sumv = reinterpret_cast<const float4*>(g_sum + (size_t)n * IN);
    const float4* xv   = reinterpret_cast<const float4*>(hin   + (size_t)n * IN);

#pragma unroll 1
    for (int kc = 0; kc < IN / 4; kc++) {
        float4 mv = sumv[kc];
        float4 rv = xv[kc];
        float m[4] = {mv.x * inv, mv.y * inv, mv.z * inv, mv.w * inv};
        float r[4] = {rv.x, rv.y, rv.z, rv.w};
#pragma unroll
        for (int i = 0; i < 4; i++) {
            int k = kc * 4 + i;
            const float4* wl = reinterpret_cast<const float4*>(sWl + k * HID);
            const float4* wr = reinterpret_cast<const float4*>(sWr + k * HID);
#pragma unroll
            for (int j4 = 0; j4 < HID / 4; j4++) {
                float4 a = wl[j4];
                float4 b = wr[j4];
                acc[j4 * 4 + 0] += m[i] * a.x + r[i] * b.x;
                acc[j4 * 4 + 1] += m[i] * a.y + r[i] * b.y;
                acc[j4 * 4 + 2] += m[i] * a.z + r[i] * b.z;
                acc[j4 * 4 + 3] += m[i] * a.w + r[i] * b.w;
            }
        }
    }

    float4* outp = reinterpret_cast<float4*>(hout + (size_t)n * HID);
#pragma unroll
    for (int j4 = 0; j4 < HID / 4; j4++) {
        float4 o;
        o.x = acc[j4 * 4 + 0]; o.y = acc[j4 * 4 + 1];
        o.z = acc[j4 * 4 + 2]; o.w = acc[j4 * 4 + 3];
        if (RELU) {
            o.x = fmaxf(o.x, 0.0f); o.y = fmaxf(o.y, 0.0f);
            o.z = fmaxf(o.z, 0.0f); o.w = fmaxf(o.w, 0.0f);
        }
        outp[j4] = o;
    }
}

// ---------------- edge MLP on mma.sync (HMMA) ----------------
// smem (bytes):
//   A1 hi/lo: 64 x STRIDE1 bf16 each   (K=144 real: k0-63 h_src, 64-127 h_dst, 128-135 ea, 136-143 zero)
//   B1 hi/lo: 64(N) x STRIDE1 bf16     (W1^T; k>=136 zero)
//   Z1 hi/lo: 64 x STRIDE2 bf16        (K2=64)
//   B2 hi/lo: 32(N) x STRIDE2 bf16     (W2^T)
//   Z2: 64 x Z2_STRIDE f32
//   biases: b1[64], b2[32], W3[32] f32
#define SM_A1H 0
#define SM_A1L (SM_A1H + 64 * STRIDE1 * 2)
#define SM_B1H (SM_A1L + 64 * STRIDE1 * 2)
#define SM_B1L (SM_B1H + 64 * STRIDE1 * 2)
#define SM_Z1H (SM_B1L + 64 * STRIDE1 * 2)
#define SM_Z1L (SM_Z1H + 64 * STRIDE2 * 2)
#define SM_B2H (SM_Z1L + 64 * STRIDE2 * 2)
#define SM_B2L (SM_B2H + 32 * STRIDE2 * 2)
#define SM_Z2  (SM_B2L + 32 * STRIDE2 * 2)
#define SM_BIA (SM_Z2 + 64 * Z2_STRIDE * 4)   // b1(64f) b2(32f) W3(32f)
#define MLP_SMEM (SM_BIA + 128 * 4)

__global__ __launch_bounds__(256)
void k_edge_mlp_mma(const float* __restrict__ h,
                    const int* __restrict__ src, const int* __restrict__ dst,
                    const float* __restrict__ ea,
                    const float* __restrict__ W1, const float* __restrict__ b1,
                    const float* __restrict__ W2, const float* __restrict__ b2,
                    const float* __restrict__ W3, const float* __restrict__ b3,
                    float* __restrict__ out) {
    extern __shared__ char sm[];
    const uint32_t sb = smem_u32(sm);

    __nv_bfloat16* pA1h = (__nv_bfloat16*)(sm + SM_A1H);
    __nv_bfloat16* pA1l = (__nv_bfloat16*)(sm + SM_A1L);
    __nv_bfloat16* pB1h = (__nv_bfloat16*)(sm + SM_B1H);
    __nv_bfloat16* pB1l = (__nv_bfloat16*)(sm + SM_B1L);
    __nv_bfloat16* pZ1h = (__nv_bfloat16*)(sm + SM_Z1H);
    __nv_bfloat16* pZ1l = (__nv_bfloat16*)(sm + SM_Z1L);
    __nv_bfloat16* pB2h = (__nv_bfloat16*)(sm + SM_B2H);
    __nv_bfloat16* pB2l = (__nv_bfloat16*)(sm + SM_B2L);
    float* pZ2 = (float*)(sm + SM_Z2);
    float* pB1b = (float*)(sm + SM_BIA);
    float* pB2b = pB1b + 64;
    float* pW3 = pB2b + 32;

    const int tid = threadIdx.x;
    const int w = tid >> 5;
    const int l = tid & 31;
    const int lrow = l & 15, lhalf = l >> 4;
    const int lg = l >> 2, lt = l & 3;       // c/a-frag group, thread-in-group

    // ---- stage weights once (persistent grid) ----
    for (int i = tid; i < 64 * 144; i += 256) {
        int j = i / 144, k = i - (i / 144) * 144;   // j = out, k = in
        float wv = (k < 136) ? W1[k * 64 + j] : 0.0f;
        __nv_bfloat16 hi, lo; bsplit(wv, hi, lo);
        pB1h[j * STRIDE1 + k] = hi;
        pB1l[j * STRIDE1 + k] = lo;
    }
    for (int i = tid; i < 32 * 64; i += 256) {
        int j = i >> 6, k = i & 63;
        float wv = W2[k * 32 + j];
        __nv_bfloat16 hi, lo; bsplit(wv, hi, lo);
        pB2h[j * STRIDE2 + k] = hi;
        pB2l[j * STRIDE2 + k] = lo;
    }
    if (tid < 64) pB1b[tid] = b1[tid];
    if (tid < 32) { pB2b[tid] = b2[tid]; pW3[tid] = W3[tid]; }
    const float bias3 = __ldg(&b3[0]);

    // gather mapping: 4 threads per edge
    const int ge = tid >> 2, gp = tid & 3;

    // warp tiles
    const int wm = w & 3, wn = w >> 2;        // stage1: m16 tile wm, n32 tile wn
    // ldmatrix base addresses (per-warp constants)
    const uint32_t aH = sb + SM_A1H + (uint32_t)(16 * wm + lrow) * (STRIDE1 * 2) + lhalf * 16;
    const uint32_t aL = aH + (SM_A1L - SM_A1H);
    const uint32_t b1H0 = sb + SM_B1H + (uint32_t)(32 * wn + lrow) * (STRIDE1 * 2) + lhalf * 16;
    const uint32_t b1H1 = b1H0 + 16 * (STRIDE1 * 2);
    const uint32_t b1L0 = b1H0 + (SM_B1L - SM_B1H);
    const uint32_t b1L1 = b1H1 + (SM_B1L - SM_B1H);
    // stage2: m16 tile wm, n16 tile wn (n offset 16*wn)
    const uint32_t zH = sb + SM_Z1H + (uint32_t)(16 * wm + lrow) * (STRIDE2 * 2) + lhalf * 16;
    const uint32_t zL = zH + (SM_Z1L - SM_Z1H);
    const uint32_t b2H = sb + SM_B2H + (uint32_t)(16 * wn + lrow) * (STRIDE2 * 2) + lhalf * 16;
    const uint32_t b2L = b2H + (SM_B2L - SM_B2H);

    for (int tile = blockIdx.x; tile < N_TILES; tile += gridDim.x) {
        const int e0 = tile * TILE_E;
        __syncthreads();   // previous tile fully consumed

        // ---- gather + split -> A1 ----
        {
            int eg = e0 + ge;
            int node = (gp < 2) ? __ldg(&src[eg]) : __ldg(&dst[eg]);
            const float4* row = reinterpret_cast<const float4*>(h + (size_t)node * HID) + (gp & 1) * 8;
            const int k0 = gp * 32;
            uint32_t dsth = sb + SM_A1H + (uint32_t)ge * (STRIDE1 * 2) + k0 * 2;
#pragma unroll
            for (int q = 0; q < 8; q++) {
                float4 v = row[q];
                __nv_bfloat16 h0, l0, h1, l1, h2, l2, h3, l3;
                bsplit(v.x, h0, l0); bsplit(v.y, h1, l1);
                bsplit(v.z, h2, l2); bsplit(v.w, h3, l3);
                uint32_t* ph = (uint32_t*)(sm + (dsth - sb) + q * 8);
                uint32_t* pl = (uint32_t*)(sm + (dsth - sb) + (SM_A1L - SM_A1H) + q * 8);
                ph[0] = packbf2(h0, h1); ph[1] = packbf2(h2, h3);
                pl[0] = packbf2(l0, l1); pl[1] = packbf2(l2, l3);
            }
            if (gp == 3) {   // edge attrs k128-135 + zero pad k136-143
                const float4* er = reinterpret_cast<const float4*>(ea + (size_t)eg * 8);
                uint32_t base = (uint32_t)ge * (STRIDE1 * 2) + 128 * 2;
#pragma unroll
                for (int q = 0; q < 2; q++) {
                    float4 v = er[q];
                    __nv_bfloat16 h0, l0, h1, l1, h2, l2, h3, l3;
                    bsplit(v.x, h0, l0); bsplit(v.y, h1, l1);
                    bsplit(v.z, h2, l2); bsplit(v.w, h3, l3);
                    uint32_t* ph = (uint32_t*)(sm + SM_A1H + base + q * 8);
                    uint32_t* pl = (uint32_t*)(sm + SM_A1L + base + q * 8);
                    ph[0] = packbf2(h0, h1); ph[1] = packbf2(h2, h3);
                    pl[0] = packbf2(l0, l1); pl[1] = packbf2(l2, l3);
                }
                uint32_t* zh = (uint32_t*)(sm + SM_A1H + base + 16);
                uint32_t* zl = (uint32_t*)(sm + SM_A1L + base + 16);
#pragma unroll
                for (int q = 0; q < 4; q++) { zh[q] = 0u; zl[q] = 0u; }
            }
        }
        __syncthreads();

        // ---- stage 1: C[64x64] = A1 @ B1 (hi*hi + hi*lo + lo*hi) ----
        float C[4][4];
#pragma unroll
        for (int j = 0; j < 4; j++)
#pragma unroll
            for (int i = 0; i < 4; i++) C[j][i] = 0.0f;

#pragma unroll 1
        for (int ks = 0; ks < 9; ks++) {
            const uint32_t ko = (uint32_t)ks * 32;
            uint32_t ah[4], al[4], bh0[4], bh1[4], bl0[4], bl1[4];
            ldsm4(aH + ko, ah);
            ldsm4(aL + ko, al);
            ldsm4(b1H0 + ko, bh0);
            ldsm4(b1H1 + ko, bh1);
            ldsm4(b1L0 + ko, bl0);
            ldsm4(b1L1 + ko, bl1);
            mma16816(C[0], ah, bh0[0], bh0[2]);
            mma16816(C[1], ah, bh0[1], bh0[3]);
            mma16816(C[2], ah, bh1[0], bh1[2]);
            mma16816(C[3], ah, bh1[1], bh1[3]);
            mma16816(C[0], ah, bl0[0], bl0[2]);
            mma16816(C[1], ah, bl0[1], bl0[3]);
            mma16816(C[2], ah, bl1[0], bl1[2]);
            mma16816(C[3], ah, bl1[1], bl1[3]);
            mma16816(C[0], al, bh0[0], bh0[2]);
            mma16816(C[1], al, bh0[1], bh0[3]);
            mma16816(C[2], al, bh1[0], bh1[2]);
            mma16816(C[3], al, bh1[1], bh1[3]);
        }

        // ---- epilogue 1: +b1, relu, split -> Z1 ----
#pragma unroll
        for (int j = 0; j < 4; j++) {
            int n = 32 * wn + 8 * j + 2 * lt;
            float bb0 = pB1b[n], bb1 = pB1b[n + 1];
            int m0 = 16 * wm + lg;
            float z00 = fmaxf(C[j][0] + bb0, 0.0f);
            float z01 = fmaxf(C[j][1] + bb1, 0.0f);
            float z10 = fmaxf(C[j][2] + bb0, 0.0f);
            float z11 = fmaxf(C[j][3] + bb1, 0.0f);
            __nv_bfloat16 h0, l0, h1, l1;
            bsplit(z00, h0, l0); bsplit(z01, h1, l1);
            *(uint32_t*)(sm + SM_Z1H + m0 * (STRIDE2 * 2) + n * 2) = packbf2(h0, h1);
            *(uint32_t*)(sm + SM_Z1L + m0 * (STRIDE2 * 2) + n * 2) = packbf2(l0, l1);
            bsplit(z10, h0, l0); bsplit(z11, h1, l1);
            *(uint32_t*)(sm + SM_Z1H + (m0 + 8) * (STRIDE2 * 2) + n * 2) = packbf2(h0, h1);
            *(uint32_t*)(sm + SM_Z1L + (m0 + 8) * (STRIDE2 * 2) + n * 2) = packbf2(l0, l1);
        }
        __syncthreads();

        // ---- stage 2: C2[64x32] = Z1 @ B2 ----
        float C2[2][4];
#pragma unroll
        for (int j = 0; j < 2; j++)
#pragma unroll
            for (int i = 0; i < 4; i++) C2[j][i] = 0.0f;

#pragma unroll
        for (int ks = 0; ks < 4; ks++) {
            const uint32_t ko = (uint32_t)ks * 32;
            uint32_t ah[4], al[4], bh[4], bl[4];
            ldsm4(zH + ko, ah);
            ldsm4(zL + ko, al);
            ldsm4(b2H + ko, bh);
            ldsm4(b2L + ko, bl);
            mma16816(C2[0], ah, bh[0], bh[2]);
            mma16816(C2[1], ah, bh[1], bh[3]);
            mma16816(C2[0], ah, bl[0], bl[2]);
            mma16816(C2[1], ah, bl[1], bl[3]);
            mma16816(C2[0], al, bh[0], bh[2]);
            mma16816(C2[1], al, bh[1], bh[3]);
        }

        // ---- epilogue 2: +b2, relu -> Z2 (f32) ----
#pragma unroll
        for (int j = 0; j < 2; j++) {
            int n = 16 * wn + 8 * j + 2 * lt;
            float bb0 = pB2b[n], bb1 = pB2b[n + 1];
            int m0 = 16 * wm + lg;
            pZ2[m0 * Z2_STRIDE + n]           = fmaxf(C2[j][0] + bb0, 0.0f);
            pZ2[m0 * Z2_STRIDE + n + 1]       = fmaxf(C2[j][1] + bb1, 0.0f);
            pZ2[(m0 + 8) * Z2_STRIDE + n]     = fmaxf(C2[j][2] + bb0, 0.0f);
            pZ2[(m0 + 8) * Z2_STRIDE + n + 1] = fmaxf(C2[j][3] + bb1, 0.0f);
        }
        __syncthreads();

        // ---- stage 3: out = sigmoid(Z2 . W3 + b3) ----
        if (tid < TILE_E) {
            float s = bias3;
            const float* zr = pZ2 + tid * Z2_STRIDE;
#pragma unroll
            for (int c = 0; c < 32; c++) s += zr[c] * pW3[c];
            out[e0 + tid] = 1.0f / (1.0f + expf(-s));
        }
    }
}

// ---------------- launch ----------------
extern "C" void kernel_launch(void* const* d_in, const int* in_sizes, int n_in,
                              void* d_out, int out_size) {
    (void)in_sizes; (void)n_in; (void)out_size;
    const float* x   = (const float*)d_in[0];
    const int*   ei  = (const int*)d_in[1];
    const float* ea  = (const float*)d_in[2];
    const float* Wl0 = (const float*)d_in[3];
    const float* bl0 = (const float*)d_in[4];
    const float* Wr0 = (const float*)d_in[5];
    const float* Wl1 = (const float*)d_in[6];
    const float* bl1 = (const float*)d_in[7];
    const float* Wr1 = (const float*)d_in[8];
    const float* Wl2 = (const float*)d_in[9];
    const float* bl2 = (const float*)d_in[10];
    const float* Wr2 = (const float*)d_in[11];
    const float* W1  = (const float*)d_in[12];
    const float* b1  = (const float*)d_in[13];
    const float* W2  = (const float*)d_in[14];
    const float* b2  = (const float*)d_in[15];
    const float* W3  = (const float*)d_in[16];
    const float* b3  = (const float*)d_in[17];
    float* out = (float*)d_out;

    const int* src = ei;
    const int* dst = ei + NE;

    void *p_deg, *p_sum, *p_hA, *p_hB;
    cudaGetSymbolAddress(&p_deg, g_deg);
    cudaGetSymbolAddress(&p_sum, g_sum);
    cudaGetSymbolAddress(&p_hA, g_hA);
    cudaGetSymbolAddress(&p_hB, g_hB);
    float* hA = (float*)p_hA;
    float* hB = (float*)p_hB;

    cudaFuncSetAttribute(k_edge_mlp_mma, cudaFuncAttributeMaxDynamicSharedMemorySize,
                         MLP_SMEM);

    cudaMemsetAsync(p_deg, 0, NN * sizeof(float), 0);
    cudaMemsetAsync(p_sum, 0, (size_t)NN * 32 * sizeof(float), 0);
    k_deg<<<(NE + 255) / 256, 256>>>(dst);

    // layer 0: IN=32
    k_scatter<32><<<(NE * 8 + 255) / 256, 256>>>(x, src, dst);
    k_node<32, true><<<(NN + 127) / 128, 128>>>(x, Wl0, bl0, Wr0, hA);

    // layer 1: IN=64
    cudaMemsetAsync(p_sum, 0, (size_t)NN * 64 * sizeof(float), 0);
    k_scatter<64><<<(NE * 16 + 255) / 256, 256>>>(hA, src, dst);
    k_node<64, true><<<(NN + 127) / 128, 128>>>(hA, Wl1, bl1, Wr1, hB);

    // layer 2: IN=64, no relu
    cudaMemsetAsync(p_sum, 0, (size_t)NN * 64 * sizeof(float), 0);
    k_scatter<64><<<(NE * 16 + 255) / 256, 256>>>(hB, src, dst);
    k_node<64, false><<<(NN + 127) / 128, 128>>>(hB, Wl2, bl2, Wr2, hA);

    // edge predictor on HMMA tensor cores
    k_edge_mlp_mma<<<MLP_GRID, 256, MLP_SMEM>>>(hA, src, dst, ea,
                                                W1, b1, W2, b2, W3, b3, out);
}